// round 16
// baseline (speedup 1.0000x reference)
#include <cuda_runtime.h>
#include <cstdint>

#define N_CLASSES 2
#define N_FEATURES 100
#define DIM 10

#define BLOCK      64
#define TILE_ROWS  64
#define F4         25                          // float4 chunks per row
#define TILE_CHUNKS (TILE_ROWS * F4)           // 1600 = BLOCK * 25 exactly
#define TILE_FLOATS (TILE_ROWS * N_FEATURES)   // 6400
#define N_M        (N_CLASSES * N_FEATURES)    // 200

// Precomputed bilinear form Re(M)[k,a]  (2 x 100 floats).
__device__ float g_Mr[N_M];

// ---------------------------------------------------------------------------
// Kernel 1: one block per output element (k,a), 200 blocks.
__global__ void compute_M_kernel(const float* __restrict__ A_re,
                                 const float* __restrict__ A_im,
                                 const float* __restrict__ psi_re,
                                 const float* __restrict__ psi_im) {
    const int k = blockIdx.x / N_FEATURES;
    const int a = blockIdx.x % N_FEATURES;
    const int tid = threadIdx.x;          // 128 threads

    __shared__ float warp_sum[4];

    float s = 0.0f;
    if (tid < DIM * DIM) {
        int i = tid / DIM, j = tid % DIM;
        float pri = psi_re[i], pii = psi_im[i];
        float prj = psi_re[j], pij = psi_im[j];
        float wr = pri * prj + pii * pij;
        float wi = pri * pij - pii * prj;
        size_t off = ((size_t)k * DIM * DIM + tid) * N_FEATURES + a;
        s = A_re[off] * wr - A_im[off] * wi;
    }
    #pragma unroll
    for (int o = 16; o > 0; o >>= 1) s += __shfl_xor_sync(0xFFFFFFFF, s, o);
    if ((tid & 31) == 0) warp_sum[tid >> 5] = s;
    __syncthreads();
    if (tid == 0)
        g_Mr[blockIdx.x] = warp_sum[0] + warp_sum[1] + warp_sum[2] + warp_sum[3];
}

// ---------------------------------------------------------------------------
__device__ __forceinline__ void cp_async16(unsigned int dst_smem, const void* src) {
    asm volatile("cp.async.cg.shared.global [%0], [%1], 16;\n"
                 :: "r"(dst_smem), "l"(src));
}
__device__ __forceinline__ void cp_async_commit_wait_all() {
    asm volatile("cp.async.commit_group;\n");
    asm volatile("cp.async.wait_group 0;\n" ::: "memory");
}

// Kernel 2: one block per 64-row tile, 8 blocks/SM resident, phase-staggered.
// Each thread issues 25 contiguous cp.async chunks (fully coalesced), then
// computes one row from smem (unpadded stride 25 float4s, odd -> conflict-free).
__global__ __launch_bounds__(BLOCK) void gemv_kernel(const float* __restrict__ x,
                                                     float2* __restrict__ out) {
    extern __shared__ float smem[];
    float* msh  = smem;                        // 2*N_FEATURES floats (800 B)
    float* tile = smem + 2 * N_FEATURES;       // TILE_FLOATS floats, unpadded

    const int tid  = threadIdx.x;
    const int row0 = blockIdx.x * TILE_ROWS;

    // Stage M into smem (50 float4 chunks; 64 threads -> one shot).
    if (tid < (2 * N_FEATURES) / 4) {
        reinterpret_cast<float4*>(msh)[tid] =
            reinterpret_cast<const float4*>(g_Mr)[tid];
    }

    // Async-load the tile: contiguous 25.6 KB region, chunk c at offset c*16.
    const float* gbase = x + (size_t)row0 * N_FEATURES;
    unsigned int tile_u32 = (unsigned int)__cvta_generic_to_shared(tile);
    #pragma unroll
    for (int k = 0; k < F4; k++) {
        int c = tid + k * BLOCK;               // 0..1599, exact cover
        cp_async16(tile_u32 + (unsigned int)c * 16, gbase + (size_t)c * 4);
    }
    cp_async_commit_wait_all();
    __syncthreads();

    // Compute: thread t -> row t of the tile (row stride 25 float4s).
    {
        const float4* xr = reinterpret_cast<const float4*>(tile) + tid * F4;
        const float4* m0 = reinterpret_cast<const float4*>(msh);
        const float4* m1 = reinterpret_cast<const float4*>(msh + N_FEATURES);
        float a0 = 0.0f, a1 = 0.0f, c0 = 0.0f, c1 = 0.0f;
        #pragma unroll
        for (int i = 0; i < F4 - 1; i += 2) {
            float4 xv = xr[i];
            float4 u  = m0[i];
            float4 v  = m1[i];
            a0 += xv.x * u.x + xv.y * u.y + xv.z * u.z + xv.w * u.w;
            c0 += xv.x * v.x + xv.y * v.y + xv.z * v.z + xv.w * v.w;
            float4 xw = xr[i + 1];
            float4 u1 = m0[i + 1];
            float4 v1 = m1[i + 1];
            a1 += xw.x * u1.x + xw.y * u1.y + xw.z * u1.z + xw.w * u1.w;
            c1 += xw.x * v1.x + xw.y * v1.y + xw.z * v1.z + xw.w * v1.w;
        }
        {   // i = 24
            float4 xv = xr[F4 - 1];
            float4 u  = m0[F4 - 1];
            float4 v  = m1[F4 - 1];
            a0 += xv.x * u.x + xv.y * u.y + xv.z * u.z + xv.w * u.w;
            c0 += xv.x * v.x + xv.y * v.y + xv.z * v.z + xv.w * v.w;
        }
        out[row0 + tid] = make_float2(a0 + a1, c0 + c1);
    }
}

// ---------------------------------------------------------------------------
extern "C" void kernel_launch(void* const* d_in, const int* in_sizes, int n_in,
                              void* d_out, int out_size) {
    const float* x      = (const float*)d_in[0];
    const float* A_re   = (const float*)d_in[1];
    const float* A_im   = (const float*)d_in[2];
    const float* psi_re = (const float*)d_in[3];
    const float* psi_im = (const float*)d_in[4];
    float2* out = (float2*)d_out;

    int T = in_sizes[0] / N_FEATURES;   // 262144

    compute_M_kernel<<<N_M, 128>>>(A_re, A_im, psi_re, psi_im);

    const int smem_bytes = (2 * N_FEATURES + TILE_FLOATS) * sizeof(float); // 26400
    cudaFuncSetAttribute(gemv_kernel,
                         cudaFuncAttributeMaxDynamicSharedMemorySize, smem_bytes);

    int grid = T / TILE_ROWS;           // 4096
    gemv_kernel<<<grid, BLOCK, smem_bytes>>>(x, out);
}

// round 17
// speedup vs baseline: 1.2594x; 1.2594x over previous
#include <cuda_runtime.h>
#include <cstdint>

#define N_CLASSES 2
#define N_FEATURES 100
#define DIM 10

#define BLOCK      64
#define TILE_ROWS  64
#define F4         25                          // float4 chunks per row
#define TILE_FLOATS (TILE_ROWS * N_FEATURES)   // 6400
#define TILE_BYTES  (TILE_FLOATS * 4)          // 25600
#define GRID       592                         // 4 persistent blocks/SM
#define N_M        (N_CLASSES * N_FEATURES)    // 200

// Precomputed bilinear form Re(M)[k,a]  (2 x 100 floats).
__device__ float g_Mr[N_M];

// ---------------------------------------------------------------------------
// Kernel 1: one block per output element (k,a), 200 blocks.
__global__ void compute_M_kernel(const float* __restrict__ A_re,
                                 const float* __restrict__ A_im,
                                 const float* __restrict__ psi_re,
                                 const float* __restrict__ psi_im) {
    const int k = blockIdx.x / N_FEATURES;
    const int a = blockIdx.x % N_FEATURES;
    const int tid = threadIdx.x;          // 128 threads

    __shared__ float warp_sum[4];

    float s = 0.0f;
    if (tid < DIM * DIM) {
        int i = tid / DIM, j = tid % DIM;
        float pri = psi_re[i], pii = psi_im[i];
        float prj = psi_re[j], pij = psi_im[j];
        float wr = pri * prj + pii * pij;
        float wi = pri * pij - pii * prj;
        size_t off = ((size_t)k * DIM * DIM + tid) * N_FEATURES + a;
        s = A_re[off] * wr - A_im[off] * wi;
    }
    #pragma unroll
    for (int o = 16; o > 0; o >>= 1) s += __shfl_xor_sync(0xFFFFFFFF, s, o);
    if ((tid & 31) == 0) warp_sum[tid >> 5] = s;
    __syncthreads();
    if (tid == 0)
        g_Mr[blockIdx.x] = warp_sum[0] + warp_sum[1] + warp_sum[2] + warp_sum[3];
}

// ---------------------------------------------------------------------------
__device__ __forceinline__ void cp_async16(unsigned int dst_smem, const void* src) {
    asm volatile("cp.async.cg.shared.global [%0], [%1], 16;\n"
                 :: "r"(dst_smem), "l"(src));
}
__device__ __forceinline__ void cp_async_commit() {
    asm volatile("cp.async.commit_group;\n");
}
template <int N>
__device__ __forceinline__ void cp_async_wait() {
    asm volatile("cp.async.wait_group %0;\n" :: "n"(N) : "memory");
}

// Issue the 25 contiguous cp.asyncs for one 64-row tile (exact cover, no
// predicates: 64 threads * 25 chunks = 1600 = tile).
__device__ __forceinline__ void issue_tile_load(const float* __restrict__ x,
                                                int tile, unsigned int buf_u32,
                                                int tid) {
    const float* gbase = x + (size_t)tile * TILE_FLOATS;
    #pragma unroll
    for (int k = 0; k < F4; k++) {
        int c = tid + k * BLOCK;               // 0..1599
        cp_async16(buf_u32 + (unsigned int)c * 16, gbase + (size_t)c * 4);
    }
    cp_async_commit();
}

// Kernel 2: persistent blocks (4/SM), double-buffered cp.async pipeline.
// While computing tile i from buffer b, tile i+stride streams into buffer b^1.
__global__ __launch_bounds__(BLOCK) void gemv_kernel(const float* __restrict__ x,
                                                     float2* __restrict__ out,
                                                     int ntiles) {
    extern __shared__ float smem[];
    float* msh = smem;                          // 2*N_FEATURES floats
    float* buf[2] = { smem + 2 * N_FEATURES,
                      smem + 2 * N_FEATURES + TILE_FLOATS };
    unsigned int buf_u32[2] = {
        (unsigned int)__cvta_generic_to_shared(buf[0]),
        (unsigned int)__cvta_generic_to_shared(buf[1]) };

    const int tid = threadIdx.x;

    // Stage M into smem (50 float4 chunks; 64 threads -> one shot).
    if (tid < (2 * N_FEATURES) / 4) {
        reinterpret_cast<float4*>(msh)[tid] =
            reinterpret_cast<const float4*>(g_Mr)[tid];
    }

    const int stride = gridDim.x;
    int tile = blockIdx.x;
    if (tile >= ntiles) return;

    // Prologue: start streaming the first tile into buffer 0.
    issue_tile_load(x, tile, buf_u32[0], tid);

    int b = 0;
    for (; tile < ntiles; tile += stride, b ^= 1) {
        int next = tile + stride;
        if (next < ntiles) {
            issue_tile_load(x, next, buf_u32[b ^ 1], tid);
            cp_async_wait<1>();   // current tile's group complete
        } else {
            cp_async_wait<0>();
        }
        __syncthreads();          // current tile visible to all threads

        // Compute: thread t -> row t of the tile (row stride 25 float4s,
        // odd -> conflict-free LDS.128).
        {
            const float4* xr = reinterpret_cast<const float4*>(buf[b]) + tid * F4;
            const float4* m0 = reinterpret_cast<const float4*>(msh);
            const float4* m1 = reinterpret_cast<const float4*>(msh + N_FEATURES);
            float a0 = 0.0f, a1 = 0.0f, c0 = 0.0f, c1 = 0.0f;
            #pragma unroll
            for (int i = 0; i < F4 - 1; i += 2) {
                float4 xv = xr[i];
                float4 u  = m0[i];
                float4 v  = m1[i];
                a0 += xv.x * u.x + xv.y * u.y + xv.z * u.z + xv.w * u.w;
                c0 += xv.x * v.x + xv.y * v.y + xv.z * v.z + xv.w * v.w;
                float4 xw = xr[i + 1];
                float4 u1 = m0[i + 1];
                float4 v1 = m1[i + 1];
                a1 += xw.x * u1.x + xw.y * u1.y + xw.z * u1.z + xw.w * u1.w;
                c1 += xw.x * v1.x + xw.y * v1.y + xw.z * v1.z + xw.w * v1.w;
            }
            {   // i = 24
                float4 xv = xr[F4 - 1];
                float4 u  = m0[F4 - 1];
                float4 v  = m1[F4 - 1];
                a0 += xv.x * u.x + xv.y * u.y + xv.z * u.z + xv.w * u.w;
                c0 += xv.x * v.x + xv.y * v.y + xv.z * v.z + xv.w * v.w;
            }
            out[tile * TILE_ROWS + tid] = make_float2(a0 + a1, c0 + c1);
        }
        __syncthreads();          // all reads of buf[b] done before refill
    }
}

// ---------------------------------------------------------------------------
extern "C" void kernel_launch(void* const* d_in, const int* in_sizes, int n_in,
                              void* d_out, int out_size) {
    const float* x      = (const float*)d_in[0];
    const float* A_re   = (const float*)d_in[1];
    const float* A_im   = (const float*)d_in[2];
    const float* psi_re = (const float*)d_in[3];
    const float* psi_im = (const float*)d_in[4];
    float2* out = (float2*)d_out;

    int T = in_sizes[0] / N_FEATURES;   // 262144
    int ntiles = T / TILE_ROWS;         // 4096

    compute_M_kernel<<<N_M, 128>>>(A_re, A_im, psi_re, psi_im);

    // 800 B M + 2 x 25600 B buffers = 52000 B per block, 4 blocks/SM = 208 KB
    const int smem_bytes = (2 * N_FEATURES + 2 * TILE_FLOATS) * sizeof(float);
    cudaFuncSetAttribute(gemv_kernel,
                         cudaFuncAttributeMaxDynamicSharedMemorySize, smem_bytes);

    gemv_kernel<<<GRID, BLOCK, smem_bytes>>>(x, out, ntiles);
}